// round 16
// baseline (speedup 1.0000x reference)
#include <cuda_runtime.h>

// ---------------------------------------------------------------------------
// LDPC damped sum-product BP, GB300 — check-sorted layout + 4-stream pipeline.
//   N_VAR=8192, N_CHK=4096, DV=3 (edge e = 3*v + j), BATCH=128, T=30.
//
// Batch split into 4 independent groups (8 float4 lanes each). Each group's
// var/chk chain runs on its own stream (event fork/join, standard capture
// pattern). Other chains' kernels fill each chain's launch gaps; memory-bound
// var phases co-schedule with MUFU-bound chk phases.
//
// Single slot-ordered message array g_MSG: chk writes C2V msg into slot i,
// var reads it and overwrites the SAME slot with f=tanh(V2C/2). Slot
// ownership unique per phase -> no hazards. V2C damping state var-ordered.
//
// Math identical to the R4/R14-validated formulation (rel_err 3.9e-7):
//   f   = sign * max(tanh(clip(V2C,-15,15)/2), eps)
//   P   = prod f ; ext = clip(P/f, +/-(1-eps)) ; msg = log((1+ext)/(1-ext))
//   out[t] = chn + sum_j C2V   (emitted by next var phase / final epilogue)
// ---------------------------------------------------------------------------

#define NVAR  8192
#define NCHK  4096
#define NE    (NVAR * 3)          // 24576
#define TITER 30
#define EPSV  1e-7f
#define NGRP  4                   // batch groups (8 float4 lanes each)

// ---- scratch state (no allocation allowed -> device globals) --------------
__device__ __align__(16) float g_MSG[NE * 128];   // slot order: f OR C2V msg
__device__ __align__(16) float g_V2C[NE * 128];   // var/edge order (linear)
__device__ int g_cnt[NCHK];
__device__ int g_off[NCHK + 1];
__device__ int g_cur[NCHK];
__device__ int g_edges[NE];       // edge ids per check (sorted -> determinism)
__device__ int g_perm[NE];        // edge id -> CSR slot
__device__ int g_bcnt[64];        // degree buckets (processing order only)
__device__ int g_bcur[64];
__device__ int g_ord[NCHK];       // checks grouped by degree (warp balance)

// ---------------------------------------------------------------------------
// CSR + degree-order build (tiny kernels, once per launch)
// ---------------------------------------------------------------------------
__global__ void zero_k() {
    int i = blockIdx.x * blockDim.x + threadIdx.x;
    if (i < NCHK) g_cnt[i] = 0;
}
__global__ void hist_k(const int* __restrict__ echk) {
    int e = blockIdx.x * blockDim.x + threadIdx.x;
    if (e < NE) atomicAdd(&g_cnt[echk[e]], 1);
}
__global__ void scan_k() {   // single block, 1024 threads, 4 counts each
    __shared__ int sh[1024];
    int t = threadIdx.x;
    if (t < 64) g_bcnt[t] = 0;                 // zero degree buckets here
    int c0 = g_cnt[4*t+0], c1 = g_cnt[4*t+1], c2 = g_cnt[4*t+2], c3 = g_cnt[4*t+3];
    int s = c0 + c1 + c2 + c3;
    sh[t] = s;
    __syncthreads();
    for (int off = 1; off < 1024; off <<= 1) {
        int v = (t >= off) ? sh[t - off] : 0;
        __syncthreads();
        sh[t] += v;
        __syncthreads();
    }
    int o = sh[t] - s;
    g_off[4*t+0] = o; g_cur[4*t+0] = o; o += c0;
    g_off[4*t+1] = o; g_cur[4*t+1] = o; o += c1;
    g_off[4*t+2] = o; g_cur[4*t+2] = o; o += c2;
    g_off[4*t+3] = o; g_cur[4*t+3] = o; o += c3;
    if (t == 1023) g_off[NCHK] = o;            // == NE
}
__global__ void scat_k(const int* __restrict__ echk) {
    int e = blockIdx.x * blockDim.x + threadIdx.x;
    if (e < NE) g_edges[atomicAdd(&g_cur[echk[e]], 1)] = e;
}
__global__ void sortperm_k() {   // per-check insertion sort + inverse perm
    int c = blockIdx.x * blockDim.x + threadIdx.x;
    if (c >= NCHK) return;
    int s = g_off[c], en = g_off[c + 1];
    for (int i = s + 1; i < en; i++) {
        int key = g_edges[i], j = i - 1;
        while (j >= s && g_edges[j] > key) { g_edges[j + 1] = g_edges[j]; j--; }
        g_edges[j + 1] = key;
    }
    for (int i = s; i < en; i++) g_perm[g_edges[i]] = i;
    int d = en - s; if (d > 63) d = 63;
    atomicAdd(&g_bcnt[d], 1);                  // degree histogram
}
__global__ void bscan_k() {      // 64-bucket exclusive scan (1 block)
    __shared__ int sh[64];
    int t = threadIdx.x;
    int v = g_bcnt[t];
    sh[t] = v;
    __syncthreads();
    for (int off = 1; off < 64; off <<= 1) {
        int x = (t >= off) ? sh[t - off] : 0;
        __syncthreads();
        sh[t] += x;
        __syncthreads();
    }
    g_bcur[t] = sh[t] - v;
}
__global__ void bplace_k() {     // scatter checks into degree order
    int c = blockIdx.x * blockDim.x + threadIdx.x;
    if (c >= NCHK) return;
    int d = g_off[c + 1] - g_off[c]; if (d > 63) d = 63;
    g_ord[atomicAdd(&g_bcur[d], 1)] = c;       // within-bucket order arbitrary
}                                              // (outputs order-independent)

// ---------------------------------------------------------------------------
__device__ __forceinline__ float4 add4(float4 a, float4 b) {
    return make_float4(a.x + b.x, a.y + b.y, a.z + b.z, a.w + b.w);
}
// f = sign * max(tanh(clip(x,-15,15)/2), eps)  (pole-correlated exp form)
__device__ __forceinline__ float fmsg(float x) {
    x = fminf(fmaxf(x, -15.0f), 15.0f);
    float E = __expf(-fabsf(x));
    float m = __fdividef(1.0f - E, 1.0f + E);
    m = fmaxf(m, EPSV);
    return (x < 0.0f) ? -m : m;
}
// msg = 2*atanh(clip(P/f)) — validated three-step form.
__device__ __forceinline__ float cmsg(float f, float P) {
    float ext = __fdividef(P, f);
    ext = fminf(fmaxf(ext, -1.0f + EPSV), 1.0f - EPSV);
    return __logf(__fdividef(1.0f + ext, 1.0f - ext));
}

// ---------------------------------------------------------------------------
// Variable phase for one batch group (8 f4 lanes): thread = (v, sub-lane).
// 64 vars/block (512 thr), 128 blocks. Gathers msg from 3 slots, emits prev
// posterior, damps V2C (linear), writes f back into the SAME 3 slots.
// ---------------------------------------------------------------------------
template <bool FIRST>
__global__ void __launch_bounds__(512) var_g(const float* __restrict__ chn,
                                             const float* __restrict__ gl,
                                             float* __restrict__ outp,
                                             int grp) {
    const int idx = blockIdx.x * 512 + threadIdx.x;
    const int v   = idx >> 3;
    const int l4  = (idx & 7) + (grp << 3);    // f4 lane within 32-f4 row
    const float gam = 1.0f / (1.0f + __expf(-gl[0]));
    const float omg = 1.0f - gam;

    const float4* CHN = (const float4*)chn;
    float4*       MSG = (float4*)g_MSG;
    float4*       V2C = (float4*)g_V2C;

    const int p0 = g_perm[3 * v + 0];
    const int p1 = g_perm[3 * v + 1];
    const int p2 = g_perm[3 * v + 2];

    const float4 Z4 = make_float4(0.f, 0.f, 0.f, 0.f);
    float4 c0 = Z4, c1 = Z4, c2 = Z4;
    if (!FIRST) {                              // 3 independent gathers (128B)
        c0 = MSG[p0 * 32 + l4];
        c1 = MSG[p1 * 32 + l4];
        c2 = MSG[p2 * 32 + l4];
    }
    float4 ch  = CHN[v * 32 + l4];
    float4 tot = add4(ch, add4(add4(c0, c1), c2));
    if (!FIRST)                                // posterior of prev iteration
        ((float4*)outp)[v * 32 + l4] = tot;

#pragma unroll
    for (int j = 0; j < 3; j++) {
        float4 cj = (j == 0) ? c0 : ((j == 1) ? c1 : c2);
        int    pj = (j == 0) ? p0 : ((j == 1) ? p1 : p2);
        int    li = (3 * v + j) * 32 + l4;     // linear V2C index
        float4 old = FIRST ? Z4 : V2C[li];
        float4 nv;
        nv.x = gam * (tot.x - cj.x) + omg * old.x;
        nv.y = gam * (tot.y - cj.y) + omg * old.y;
        nv.z = gam * (tot.z - cj.z) + omg * old.z;
        nv.w = gam * (tot.w - cj.w) + omg * old.w;
        V2C[li] = nv;
        float4 fv = make_float4(fmsg(nv.x), fmsg(nv.y), fmsg(nv.z), fmsg(nv.w));
        MSG[pj * 32 + l4] = fv;                // overwrite slot with f
    }
}

// ---------------------------------------------------------------------------
// Check phase for one group: thread = (check, sub-lane); checks degree-
// grouped via g_ord so the 4 checks in a warp have matching trip counts.
// Slot rows contiguous -> streaming. 64 checks/block, 64 blocks.
// ---------------------------------------------------------------------------
__global__ void __launch_bounds__(512) chk_g(int grp) {
    const int idx = blockIdx.x * 512 + threadIdx.x;
    const int c   = g_ord[idx >> 3];
    const int l4  = (idx & 7) + (grp << 3);
    const int s   = g_off[c];
    const int en  = g_off[c + 1];

    float4* MSG = (float4*)g_MSG;

    float4 P = make_float4(1.f, 1.f, 1.f, 1.f);
#pragma unroll 4
    for (int i = s; i < en; i++) {             // contiguous rows
        float4 f = MSG[i * 32 + l4];
        P.x *= f.x; P.y *= f.y; P.z *= f.z; P.w *= f.w;
    }
#pragma unroll 4
    for (int i = s; i < en; i++) {
        float4 f = MSG[i * 32 + l4];           // L1 hit
        float4 m;
        m.x = cmsg(f.x, P.x);
        m.y = cmsg(f.y, P.y);
        m.z = cmsg(f.z, P.z);
        m.w = cmsg(f.w, P.w);
        MSG[i * 32 + l4] = m;                  // overwrite slot with msg
    }
}

// Final posterior (iteration T-1) for one group.
__global__ void __launch_bounds__(512) out_g(const float* __restrict__ chn,
                                             float* __restrict__ outp,
                                             int grp) {
    const int idx = blockIdx.x * 512 + threadIdx.x;
    const int v   = idx >> 3;
    const int l4  = (idx & 7) + (grp << 3);
    const float4* MSG = (const float4*)g_MSG;
    float4 c0 = MSG[g_perm[3 * v + 0] * 32 + l4];
    float4 c1 = MSG[g_perm[3 * v + 1] * 32 + l4];
    float4 c2 = MSG[g_perm[3 * v + 2] * 32 + l4];
    ((float4*)outp)[v * 32 + l4] =
        add4(((const float4*)chn)[v * 32 + l4], add4(add4(c0, c1), c2));
}

// ---------------------------------------------------------------------------
static void run_group_chain(cudaStream_t st, int grp, const float* chn,
                            const float* gl, float* out) {
    const size_t OSZ = (size_t)NVAR * 128;
    const dim3 VG(NVAR * 8 / 512), CG(NCHK * 8 / 512), TB(512);
    var_g<true><<<VG, TB, 0, st>>>(chn, gl, nullptr, grp);
    chk_g      <<<CG, TB, 0, st>>>(grp);
    for (int t = 1; t < TITER; t++) {
        var_g<false><<<VG, TB, 0, st>>>(chn, gl, out + (size_t)(t - 1) * OSZ, grp);
        chk_g      <<<CG, TB, 0, st>>>(grp);
    }
    out_g<<<VG, TB, 0, st>>>(chn, out + (size_t)(TITER - 1) * OSZ, grp);
}

extern "C" void kernel_launch(void* const* d_in, const int* in_sizes, int n_in,
                              void* d_out, int out_size) {
    (void)in_sizes; (void)n_in; (void)out_size;
    const float* chn  = (const float*)d_in[0];   // (8192, 128) f32
    const float* gl   = (const float*)d_in[1];   // (1,)        f32
    const int*   echk = (const int*)d_in[3];     // (24576,)    i32
    float*       out  = (float*)d_out;           // (30, 8192, 128) f32

    // One-time stream/event setup. Created only when NOT capturing (the
    // harness's first call is the uncaptured correctness run). If somehow
    // first invoked under capture, fall back to the single-stream path.
    static cudaStream_t s[NGRP - 1] = {};
    static cudaEvent_t  evF = nullptr, evJ[NGRP - 1] = {};
    if (!s[0]) {
        cudaStreamCaptureStatus cs = cudaStreamCaptureStatusNone;
        cudaStreamIsCapturing(0, &cs);
        if (cs == cudaStreamCaptureStatusNone) {
            for (int i = 0; i < NGRP - 1; i++) {
                cudaStreamCreateWithFlags(&s[i], cudaStreamNonBlocking);
                cudaEventCreateWithFlags(&evJ[i], cudaEventDisableTiming);
            }
            cudaEventCreateWithFlags(&evF, cudaEventDisableTiming);
        }
    }

    // ---- CSR + degree-order build (origin stream) -------------------------
    zero_k    <<<(NCHK + 255) / 256, 256>>>();
    hist_k    <<<(NE   + 255) / 256, 256>>>(echk);
    scan_k    <<<1, 1024>>>();
    scat_k    <<<(NE   + 255) / 256, 256>>>(echk);
    sortperm_k<<<(NCHK + 255) / 256, 256>>>();
    bscan_k   <<<1, 64>>>();
    bplace_k  <<<(NCHK + 255) / 256, 256>>>();

    if (s[0]) {
        // fork: groups 1..3 on side streams, group 0 on origin stream
        cudaEventRecord(evF, 0);
        for (int i = 0; i < NGRP - 1; i++) cudaStreamWaitEvent(s[i], evF, 0);
        run_group_chain(0, 0, chn, gl, out);
        for (int i = 0; i < NGRP - 1; i++)
            run_group_chain(s[i], i + 1, chn, gl, out);
        // join
        for (int i = 0; i < NGRP - 1; i++) {
            cudaEventRecord(evJ[i], s[i]);
            cudaStreamWaitEvent(0, evJ[i], 0);
        }
    } else {
        // capture-safe fallback: sequential groups on the origin stream
        for (int g = 0; g < NGRP; g++) run_group_chain(0, g, chn, gl, out);
    }
}